// round 11
// baseline (speedup 1.0000x reference)
#include <cuda_runtime.h>
#include <math.h>

#define NSP 9216        // 16*24*24
#define DD 16
#define HH 24
#define WW 24
#define PROW 26         // padded row (W+2)
#define PPLN 676        // padded plane (H+2)*(W+2)
#define PCH  12168      // padded channel (D+2)*PPLN
#define KS 16           // key splits for attention
#define KPS (NSP / KS)  // 576 keys per split
#define ESHIFT 40.0f    // fixed softmax shift

typedef unsigned long long ull;

// ---------------- f32x2 packed helpers (sm_100+) ---------------------------
__device__ __forceinline__ ull pack2(float lo, float hi) {
    ull r;
    asm("mov.b64 %0, {%1, %2};" : "=l"(r) : "f"(lo), "f"(hi));
    return r;
}
__device__ __forceinline__ float2 unpack2(ull v) {
    float2 f;
    asm("mov.b64 {%0, %1}, %2;" : "=f"(f.x), "=f"(f.y) : "l"(v));
    return f;
}
__device__ __forceinline__ void fma2(ull& d, ull a, ull b) {
    asm("fma.rn.f32x2 %0, %1, %2, %3;" : "=l"(d) : "l"(a), "l"(b), "l"(d));
}
__device__ __forceinline__ ull mul2(ull a, ull b) {
    ull r;
    asm("mul.rn.f32x2 %0, %1, %2;" : "=l"(r) : "l"(a), "l"(b));
    return r;
}

// ---------------- scratch (device globals; zero-initialized) ---------------
__device__ __align__(16) float d_xpad[64 * PCH];      // padded x (borders 0)
__device__ __align__(16) float d_ogpad[32 * PCH];     // padded attn out
__device__ __align__(16) float d_thetaA[NSP * 8];     // ci 0-31 partial
__device__ __align__(16) float d_thetaB[NSP * 8];     // ci 32-63 partial
__device__ __align__(16) float d_phiA[NSP * 8];
__device__ __align__(16) float d_phiB[NSP * 8];
__device__ __align__(16) float d_gA[NSP * 32];
__device__ __align__(16) float d_gB[NSP * 32];
__device__ __align__(16) float d_pl[KS * NSP];        // partial sum
__device__ __align__(16) float d_pacc[KS * NSP * 32]; // partial acc
__device__ __align__(16) float d_yA[64 * NSP];        // o-conv ci 0-15
__device__ __align__(16) float d_yB[64 * NSP];        // o-conv ci 16-31
__device__ float d_mean[64];
__device__ float d_rstd[64];

// tap offsets into padded layout (compile-time immediates after unroll)
#define TAPOFF(t) ((t / 9) * PPLN + ((t / 3) % 3) * PROW + (t % 3))

// ---------------- kernel 0: pad x into halo layout -------------------------
__global__ __launch_bounds__(256) void pad_x(const float* __restrict__ x)
{
    const int idx = blockIdx.x * 256 + threadIdx.x;
    if (idx >= 64 * NSP) return;
    const int c = idx / NSP, n = idx % NSP;
    const int d = n / (HH * WW), r = n % (HH * WW);
    const int h = r / WW, w = r % WW;
    d_xpad[c * PCH + (d + 1) * PPLN + (h + 1) * PROW + (w + 1)] = x[idx];
}

// ---------------- kernel 1: fused theta/phi/g conv3d, ci-split -------------
// grid: (96, 12): gy%6 = role (0 theta, 1 phi, 2-5 g), gy/6 = ci half
__global__ __launch_bounds__(96) void conv_qkv(
    const float* __restrict__ tw, const float* __restrict__ tb,
    const float* __restrict__ pw, const float* __restrict__ pb,
    const float* __restrict__ gw, const float* __restrict__ gb)
{
    __shared__ __align__(16) float ws[16 * 27 * 8];   // [ci][tap][co]

    const int tid  = threadIdx.x;
    const int role = blockIdx.y % 6;
    const int half = blockIdx.y / 6;
    const int d = blockIdx.x / 6;
    const int h = (blockIdx.x % 6) * 4 + tid / 24;
    const int w = tid % 24;
    const int corner = d * PPLN + h * PROW + w;

    ull acc2[4];
#pragma unroll
    for (int j = 0; j < 4; j++) acc2[j] = 0ull;

    for (int cc = 0; cc < 2; cc++) {          // 2 chunks of 16 ci (32 total)
        for (int i = tid; i < 16 * 27 * 8; i += 96) {
            const int ci  = i / (27 * 8);
            const int rem = i % (27 * 8);
            const int tap = rem / 8;
            const int co  = rem % 8;
            const int cig = half * 32 + cc * 16 + ci;
            float v;
            if (role == 0)      v = tw[(co * 64 + cig) * 27 + tap];
            else if (role == 1) v = pw[(co * 64 + cig) * 27 + tap];
            else v = gw[(((role - 2) * 8 + co) * 64 + cig) * 27 + tap];
            ws[(ci * 27 + tap) * 8 + co] = v;
        }
        __syncthreads();

        for (int ci = 0; ci < 16; ci++) {
            const float* xb =
                d_xpad + (half * 32 + cc * 16 + ci) * PCH + corner;
            float xv[27];
#pragma unroll
            for (int t = 0; t < 27; t++)
                xv[t] = __ldg(xb + TAPOFF(t));
#pragma unroll
            for (int t = 0; t < 27; t++) {
                const ull x2 = pack2(xv[t], xv[t]);
                const ulonglong2 wv =
                    *(const ulonglong2*)&ws[(ci * 27 + t) * 8];
                fma2(acc2[0], x2, wv.x);
                fma2(acc2[1], x2, wv.y);
                const ulonglong2 wv2 =
                    *(const ulonglong2*)&ws[(ci * 27 + t) * 8 + 4];
                fma2(acc2[2], x2, wv2.x);
                fma2(acc2[3], x2, wv2.y);
            }
        }
        __syncthreads();
    }

    float acc[8];
#pragma unroll
    for (int j = 0; j < 4; j++) {
        float2 u = unpack2(acc2[j]);
        acc[2 * j] = u.x; acc[2 * j + 1] = u.y;
    }

    const int n = d * (HH * WW) + h * WW + w;
    if (role == 0) {
        float* dst = half ? d_thetaB : d_thetaA;
#pragma unroll
        for (int c = 0; c < 8; c++)
            dst[n * 8 + c] = acc[c] + (half ? 0.f : tb[c]);
    } else if (role == 1) {
        float* dst = half ? d_phiB : d_phiA;
#pragma unroll
        for (int c = 0; c < 8; c++)
            dst[n * 8 + c] = acc[c] + (half ? 0.f : pb[c]);
    } else {
        float* dst = half ? d_gB : d_gA;
        const int cb = (role - 2) * 8;
#pragma unroll
        for (int c = 0; c < 8; c++)
            dst[n * 32 + cb + c] = acc[c] + (half ? 0.f : gb[cb + c]);
    }
}

// ---------------- kernel 2: single-pass shifted-exp attention --------------
// grid: (72, KS), block: 128; ONE query per thread (max warps in flight)
__global__ __launch_bounds__(128) void attn_split()
{
    __shared__ __align__(16) float ps[64 * 8];    // phi tile
    __shared__ __align__(16) float gs[64 * 32];   // g tile
    const int t  = threadIdx.x;
    const int q  = blockIdx.x * 128 + t;
    const int k0 = blockIdx.y * KPS;

    ull th[4];
    {
        const float4* tA = (const float4*)&d_thetaA[q * 8];
        const float4* tB = (const float4*)&d_thetaB[q * 8];
        float4 a0 = tA[0], a1 = tA[1], b0 = tB[0], b1 = tB[1];
        th[0] = pack2(a0.x + b0.x, a0.y + b0.y);
        th[1] = pack2(a0.z + b0.z, a0.w + b0.w);
        th[2] = pack2(a1.x + b1.x, a1.y + b1.y);
        th[3] = pack2(a1.z + b1.z, a1.w + b1.w);
    }

    float l = 0.f;
    ull acc[16];
#pragma unroll
    for (int j = 0; j < 16; j++) acc[j] = 0ull;

    for (int kt = 0; kt < KPS / 64; kt++) {
        __syncthreads();
        {
            const float4* fA = (const float4*)(d_phiA + (k0 + kt * 64) * 8);
            const float4* fB = (const float4*)(d_phiB + (k0 + kt * 64) * 8);
            float4 a = fA[t], b = fB[t];
            ((float4*)ps)[t] =
                make_float4(a.x + b.x, a.y + b.y, a.z + b.z, a.w + b.w);
        }
        {
            const float4* gA = (const float4*)(d_gA + (k0 + kt * 64) * 32);
            const float4* gB = (const float4*)(d_gB + (k0 + kt * 64) * 32);
#pragma unroll
            for (int i = 0; i < 4; i++) {
                float4 a = gA[t + i * 128], b = gB[t + i * 128];
                ((float4*)gs)[t + i * 128] =
                    make_float4(a.x + b.x, a.y + b.y, a.z + b.z, a.w + b.w);
            }
        }
        __syncthreads();

#pragma unroll 2
        for (int k = 0; k < 64; k++) {
            const ulonglong2* pp = (const ulonglong2*)&ps[k * 8];
            const ulonglong2 pA = pp[0], pB = pp[1];

            ull s2 = mul2(th[0], pA.x);
            fma2(s2, th[1], pA.y); fma2(s2, th[2], pB.x); fma2(s2, th[3], pB.y);
            float2 sf = unpack2(s2);

            const float p = __expf(sf.x + sf.y - ESHIFT);
            l += p;
            const ull p2 = pack2(p, p);

            const ulonglong2* gg = (const ulonglong2*)&gs[k * 32];
#pragma unroll
            for (int j = 0; j < 8; j++) {
                ulonglong2 gv = gg[j];
                fma2(acc[2 * j],     p2, gv.x);
                fma2(acc[2 * j + 1], p2, gv.y);
            }
        }
    }

    const int ks = blockIdx.y;
    d_pl[ks * NSP + q] = l;
    ulonglong2* pa = (ulonglong2*)&d_pacc[((size_t)ks * NSP + q) * 32];
#pragma unroll
    for (int j = 0; j < 8; j++)
        pa[j] = make_ulonglong2(acc[2 * j], acc[2 * j + 1]);
}

// ---------------- kernel 3: merge splits, channel-parallel -----------------
// grid: (72, 8), block 128 — each block handles 4 of 32 channels
__global__ __launch_bounds__(128) void attn_combine()
{
    const int q  = blockIdx.x * 128 + threadIdx.x;
    const int cb = blockIdx.y * 4;

    float l = 0.f;
#pragma unroll
    for (int i = 0; i < KS; i++) l += d_pl[i * NSP + q];

    float a0 = 0.f, a1 = 0.f, a2 = 0.f, a3 = 0.f;
#pragma unroll
    for (int i = 0; i < KS; i++) {
        float4 v = *(const float4*)&d_pacc[((size_t)i * NSP + q) * 32 + cb];
        a0 += v.x; a1 += v.y; a2 += v.z; a3 += v.w;
    }

    const float inv = 1.f / l;
    const int d = q / (HH * WW), r = q % (HH * WW);
    const int pidx = (d + 1) * PPLN + (r / WW + 1) * PROW + (r % WW + 1);
    d_ogpad[(cb + 0) * PCH + pidx] = a0 * inv;
    d_ogpad[(cb + 1) * PCH + pidx] = a1 * inv;
    d_ogpad[(cb + 2) * PCH + pidx] = a2 * inv;
    d_ogpad[(cb + 3) * PCH + pidx] = a3 * inv;
}

// ---------------- kernel 4: o-conv, ci-split -------------------------------
// grid: (96, 16): gy%8 = co-group of 8, gy/8 = ci half (16 each)
__global__ __launch_bounds__(96) void conv_o(
    const float* __restrict__ ow, const float* __restrict__ ob)
{
    __shared__ __align__(16) float ws[16 * 27 * 8];

    const int tid  = threadIdx.x;
    const int gyco = blockIdx.y % 8;
    const int half = blockIdx.y / 8;
    const int d = blockIdx.x / 6;
    const int h = (blockIdx.x % 6) * 4 + tid / 24;
    const int w = tid % 24;
    const int corner = d * PPLN + h * PROW + w;

    ull acc2[4];
#pragma unroll
    for (int j = 0; j < 4; j++) acc2[j] = 0ull;

    for (int i = tid; i < 16 * 27 * 8; i += 96) {
        const int ci  = i / (27 * 8);
        const int rem = i % (27 * 8);
        const int tap = rem / 8;
        const int co  = rem % 8;
        ws[(ci * 27 + tap) * 8 + co] =
            ow[((gyco * 8 + co) * 32 + half * 16 + ci) * 27 + tap];
    }
    __syncthreads();

    for (int ci = 0; ci < 16; ci++) {
        const float* xb = d_ogpad + (half * 16 + ci) * PCH + corner;
        float xv[27];
#pragma unroll
        for (int t = 0; t < 27; t++)
            xv[t] = __ldg(xb + TAPOFF(t));
#pragma unroll
        for (int t = 0; t < 27; t++) {
            const ull x2 = pack2(xv[t], xv[t]);
            const ulonglong2 wv = *(const ulonglong2*)&ws[(ci * 27 + t) * 8];
            fma2(acc2[0], x2, wv.x);
            fma2(acc2[1], x2, wv.y);
            const ulonglong2 wv2 =
                *(const ulonglong2*)&ws[(ci * 27 + t) * 8 + 4];
            fma2(acc2[2], x2, wv2.x);
            fma2(acc2[3], x2, wv2.y);
        }
    }

    const int n = d * (HH * WW) + h * WW + w;
    float* dst = half ? d_yB : d_yA;
#pragma unroll
    for (int j = 0; j < 4; j++) {
        float2 u = unpack2(acc2[j]);
        const int c0 = gyco * 8 + 2 * j;
        dst[c0 * NSP + n]       = u.x + (half ? 0.f : ob[c0]);
        dst[(c0 + 1) * NSP + n] = u.y + (half ? 0.f : ob[c0 + 1]);
    }
}

// ---------------- kernel 5: BN stats (512 thr, sums A+B) -------------------
__global__ __launch_bounds__(512) void bn_stats()
{
    const int c = blockIdx.x;
    float s = 0.f, s2 = 0.f;
    const float4* ya = (const float4*)&d_yA[c * NSP];
    const float4* yb = (const float4*)&d_yB[c * NSP];
    for (int i = threadIdx.x; i < NSP / 4; i += 512) {
        float4 a = ya[i], b = yb[i];
        float vx = a.x + b.x, vy = a.y + b.y, vz = a.z + b.z, vw = a.w + b.w;
        s  += vx + vy + vz + vw;
        s2 += vx * vx + vy * vy + vz * vz + vw * vw;
    }
#pragma unroll
    for (int o = 16; o > 0; o >>= 1) {
        s  += __shfl_down_sync(0xffffffffu, s,  o);
        s2 += __shfl_down_sync(0xffffffffu, s2, o);
    }
    __shared__ float shs[16], shs2[16];
    const int wid = threadIdx.x / 32, lid = threadIdx.x % 32;
    if (lid == 0) { shs[wid] = s; shs2[wid] = s2; }
    __syncthreads();
    if (threadIdx.x == 0) {
        float ts = 0.f, ts2 = 0.f;
#pragma unroll
        for (int i = 0; i < 16; i++) { ts += shs[i]; ts2 += shs2[i]; }
        const float mean = ts * (1.f / NSP);
        const float var  = ts2 * (1.f / NSP) - mean * mean;
        d_mean[c] = mean;
        d_rstd[c] = rsqrtf(var + 1e-5f);
    }
}

// ---------------- kernel 6: BN apply + residual + relu ---------------------
__global__ __launch_bounds__(256) void final_ew(
    const float* __restrict__ x,
    const float* __restrict__ gamma,
    const float* __restrict__ beta,
    float* __restrict__ out)
{
    const int idx = blockIdx.x * 256 + threadIdx.x;
    if (idx >= 64 * NSP) return;
    const int c = idx / NSP;
    const float y = d_yA[idx] + d_yB[idx];
    const float yn = (y - d_mean[c]) * d_rstd[c] * gamma[c] + beta[c];
    const float v  = x[idx] + yn;
    out[idx] = v > 0.f ? v : 0.f;
}

// ---------------- launch ---------------------------------------------------
extern "C" void kernel_launch(void* const* d_in, const int* in_sizes, int n_in,
                              void* d_out, int out_size)
{
    (void)in_sizes; (void)n_in; (void)out_size;
    const float* x  = (const float*)d_in[0];
    const float* tw = (const float*)d_in[1];
    const float* tb = (const float*)d_in[2];
    const float* pw = (const float*)d_in[3];
    const float* pb = (const float*)d_in[4];
    const float* gw = (const float*)d_in[5];
    const float* gb = (const float*)d_in[6];
    const float* ow = (const float*)d_in[7];
    const float* ob = (const float*)d_in[8];
    const float* gamma = (const float*)d_in[9];
    const float* beta  = (const float*)d_in[10];
    float* out = (float*)d_out;

    pad_x<<<(64 * NSP + 255) / 256, 256>>>(x);
    conv_qkv<<<dim3(96, 12), 96>>>(tw, tb, pw, pb, gw, gb);
    attn_split<<<dim3(NSP / 128, KS), 128>>>();
    attn_combine<<<dim3(NSP / 128, 8), 128>>>();
    conv_o<<<dim3(96, 16), 96>>>(ow, ob);
    bn_stats<<<64, 512>>>();
    final_ew<<<(64 * NSP + 255) / 256, 256>>>(x, gamma, beta, out);
}

// round 12
// speedup vs baseline: 1.2708x; 1.2708x over previous
#include <cuda_runtime.h>
#include <math.h>

#define NSP 9216        // 16*24*24
#define DD 16
#define HH 24
#define WW 24
#define PROW 26         // padded row (W+2)
#define PPLN 676        // padded plane (H+2)*(W+2)
#define PCH  12168      // padded channel (D+2)*PPLN
#define KS 16           // key splits for attention
#define KPS (NSP / KS)  // 576 keys per split
#define ESHIFT 40.0f    // fixed softmax shift

typedef unsigned long long ull;

// ---------------- f32x2 packed helpers (sm_100+) ---------------------------
__device__ __forceinline__ ull pack2(float lo, float hi) {
    ull r;
    asm("mov.b64 %0, {%1, %2};" : "=l"(r) : "f"(lo), "f"(hi));
    return r;
}
__device__ __forceinline__ float2 unpack2(ull v) {
    float2 f;
    asm("mov.b64 {%0, %1}, %2;" : "=f"(f.x), "=f"(f.y) : "l"(v));
    return f;
}
__device__ __forceinline__ void fma2(ull& d, ull a, ull b) {
    asm("fma.rn.f32x2 %0, %1, %2, %3;" : "=l"(d) : "l"(a), "l"(b), "l"(d));
}
__device__ __forceinline__ ull mul2(ull a, ull b) {
    ull r;
    asm("mul.rn.f32x2 %0, %1, %2;" : "=l"(r) : "l"(a), "l"(b));
    return r;
}
__device__ __forceinline__ unsigned f2tf32(float f) {
    unsigned u;
    asm("cvt.rna.tf32.f32 %0, %1;" : "=r"(u) : "f"(f));
    return u;
}
// D += A(p, 16x8) @ B(g, 8x8), tf32 inputs, f32 accum
__device__ __forceinline__ void mma_tf32(float* d,
    unsigned a0, unsigned a1, unsigned a2, unsigned a3,
    unsigned b0, unsigned b1) {
    asm("mma.sync.aligned.m16n8k8.row.col.f32.tf32.tf32.f32 "
        "{%0,%1,%2,%3}, {%4,%5,%6,%7}, {%8,%9}, {%0,%1,%2,%3};"
        : "+f"(d[0]), "+f"(d[1]), "+f"(d[2]), "+f"(d[3])
        : "r"(a0), "r"(a1), "r"(a2), "r"(a3), "r"(b0), "r"(b1));
}

// ---------------- scratch (device globals; zero-initialized) ---------------
__device__ __align__(16) float d_xpad[64 * PCH];      // padded x (borders 0)
__device__ __align__(16) float d_ogpad[32 * PCH];     // padded attn out
__device__ __align__(16) float d_theta[NSP * 8];      // [n][c]
__device__ __align__(16) float d_phi[NSP * 8];        // [n][c]
__device__ __align__(16) float d_g[NSP * 32];         // [n][c]
__device__ __align__(16) float d_pl[KS * NSP];        // partial sum
__device__ __align__(16) float d_pacc[KS * NSP * 32]; // partial acc
__device__ __align__(16) float d_y[64 * NSP];         // o-conv out, [c][n]
__device__ float d_mean[64];
__device__ float d_rstd[64];

// tap offsets into padded layout (compile-time immediates after unroll)
#define TAPOFF(t) ((t / 9) * PPLN + ((t / 3) % 3) * PROW + (t % 3))

// ---------------- kernel 0: pad x into halo layout -------------------------
__global__ __launch_bounds__(256) void pad_x(const float* __restrict__ x)
{
    const int idx = blockIdx.x * 256 + threadIdx.x;
    if (idx >= 64 * NSP) return;
    const int c = idx / NSP, n = idx % NSP;
    const int d = n / (HH * WW), r = n % (HH * WW);
    const int h = r / WW, w = r % WW;
    d_xpad[c * PCH + (d + 1) * PPLN + (h + 1) * PROW + (w + 1)] = x[idx];
}

// ---------------- kernel 1: fused theta/phi/g conv3d -----------------------
// grid: (96, 6) — 96 spatial tiles (1x4x24), 6 co-groups of 8
__global__ __launch_bounds__(96) void conv_qkv(
    const float* __restrict__ tw, const float* __restrict__ tb,
    const float* __restrict__ pw, const float* __restrict__ pb,
    const float* __restrict__ gw, const float* __restrict__ gb)
{
    __shared__ __align__(16) float ws[16 * 27 * 8];   // [ci][tap][co]

    const int tid = threadIdx.x;
    const int gy = blockIdx.y;
    const int d = blockIdx.x / 6;
    const int h = (blockIdx.x % 6) * 4 + tid / 24;
    const int w = tid % 24;
    const int corner = d * PPLN + h * PROW + w;

    ull acc2[4];
#pragma unroll
    for (int j = 0; j < 4; j++) acc2[j] = 0ull;

    for (int cc = 0; cc < 4; cc++) {          // ci chunks of 16
        for (int i = tid; i < 16 * 27 * 8; i += 96) {
            const int ci  = i / (27 * 8);
            const int rem = i % (27 * 8);
            const int tap = rem / 8;
            const int co  = rem % 8;
            const int cig = cc * 16 + ci;
            float v;
            if (gy == 0)      v = tw[(co * 64 + cig) * 27 + tap];
            else if (gy == 1) v = pw[(co * 64 + cig) * 27 + tap];
            else              v = gw[(((gy - 2) * 8 + co) * 64 + cig) * 27 + tap];
            ws[(ci * 27 + tap) * 8 + co] = v;
        }
        __syncthreads();

        for (int ci = 0; ci < 16; ci++) {
            const float* xb = d_xpad + (cc * 16 + ci) * PCH + corner;
            float xv[27];
#pragma unroll
            for (int t = 0; t < 27; t++)
                xv[t] = __ldg(xb + TAPOFF(t));
#pragma unroll
            for (int t = 0; t < 27; t++) {
                const ull x2 = pack2(xv[t], xv[t]);
                const ulonglong2 wv =
                    *(const ulonglong2*)&ws[(ci * 27 + t) * 8];
                fma2(acc2[0], x2, wv.x);
                fma2(acc2[1], x2, wv.y);
                const ulonglong2 wv2 =
                    *(const ulonglong2*)&ws[(ci * 27 + t) * 8 + 4];
                fma2(acc2[2], x2, wv2.x);
                fma2(acc2[3], x2, wv2.y);
            }
        }
        __syncthreads();
    }

    float acc[8];
#pragma unroll
    for (int j = 0; j < 4; j++) {
        float2 u = unpack2(acc2[j]);
        acc[2 * j] = u.x; acc[2 * j + 1] = u.y;
    }

    const int n = d * (HH * WW) + h * WW + w;
    if (gy == 0) {
#pragma unroll
        for (int c = 0; c < 8; c++) d_theta[n * 8 + c] = acc[c] + tb[c];
    } else if (gy == 1) {
#pragma unroll
        for (int c = 0; c < 8; c++) d_phi[n * 8 + c] = acc[c] + pb[c];
    } else {
        const int cb = (gy - 2) * 8;
#pragma unroll
        for (int c = 0; c < 8; c++)
            d_g[n * 32 + cb + c] = acc[c] + gb[cb + c];
    }
}

// ---------------- kernel 2: attention, fp32 scores + tf32 mma PV -----------
// grid: (72, KS), block 256 (8 warps). Warp owns 16 queries.
// Per 8-key step: each thread computes 4 scores in the m16n8k8 A-fragment
// arrangement (rows lane/4, lane/4+8; cols lane%4, lane%4+4), exps them,
// and feeds 4 tf32 mmas (one per 8-channel g group). l stays scalar fp32.
__global__ __launch_bounds__(256) void attn_split()
{
    __shared__ __align__(16) float    ps[64 * 8];    // phi tile (fp32)
    __shared__ __align__(16) unsigned gs[64 * 32];   // g tile (tf32 bits)

    const int t = threadIdx.x;
    const int warp = t / 32, lane = t % 32;
    const int r = lane / 4, j = lane % 4;
    const int q0 = blockIdx.x * 128 + warp * 16;     // warp's query base
    const int k0 = blockIdx.y * KPS;

    // theta rows q0+r and q0+r+8 (f32x2 packed)
    ull thA[4], thB[4];
    {
        const float4* pA = (const float4*)&d_theta[(q0 + r) * 8];
        float4 a0 = pA[0], a1 = pA[1];
        thA[0] = pack2(a0.x, a0.y); thA[1] = pack2(a0.z, a0.w);
        thA[2] = pack2(a1.x, a1.y); thA[3] = pack2(a1.z, a1.w);
        const float4* pB = (const float4*)&d_theta[(q0 + 8 + r) * 8];
        float4 b0 = pB[0], b1 = pB[1];
        thB[0] = pack2(b0.x, b0.y); thB[1] = pack2(b0.z, b0.w);
        thB[2] = pack2(b1.x, b1.y); thB[3] = pack2(b1.z, b1.w);
    }

    float dacc[4][4];   // 4 channel groups x 4 C regs
#pragma unroll
    for (int g2 = 0; g2 < 4; g2++)
#pragma unroll
        for (int c = 0; c < 4; c++) dacc[g2][c] = 0.f;
    float lr = 0.f, lr8 = 0.f;

    for (int kt = 0; kt < KPS / 64; kt++) {
        __syncthreads();
        if (t < 128)
            ((float4*)ps)[t] = ((const float4*)(d_phi + (k0 + kt * 64) * 8))[t];
        {
            const float4* src = (const float4*)(d_g + (k0 + kt * 64) * 32);
#pragma unroll
            for (int i = 0; i < 2; i++) {
                float4 v = src[t + i * 256];
                uint4 u;
                u.x = f2tf32(v.x); u.y = f2tf32(v.y);
                u.z = f2tf32(v.z); u.w = f2tf32(v.w);
                ((uint4*)gs)[t + i * 256] = u;
            }
        }
        __syncthreads();

#pragma unroll 2
        for (int sub = 0; sub < 8; sub++) {
            const int kb = sub * 8;
            // phi for keys kb+j and kb+j+4
            const ulonglong2* ph0 = (const ulonglong2*)&ps[(kb + j) * 8];
            const ulonglong2* ph1 = (const ulonglong2*)&ps[(kb + j + 4) * 8];
            const ulonglong2 f0 = ph0[0], f1 = ph0[1];
            const ulonglong2 g0 = ph1[0], g1 = ph1[1];

            // 4 scores (A-fragment positions)
            ull s;
            s = mul2(thA[0], f0.x); fma2(s, thA[1], f0.y);
            fma2(s, thA[2], f1.x);  fma2(s, thA[3], f1.y);
            float2 u = unpack2(s);  const float s00 = u.x + u.y;   // (r,   j)
            s = mul2(thB[0], f0.x); fma2(s, thB[1], f0.y);
            fma2(s, thB[2], f1.x);  fma2(s, thB[3], f1.y);
            u = unpack2(s);         const float s10 = u.x + u.y;   // (r+8, j)
            s = mul2(thA[0], g0.x); fma2(s, thA[1], g0.y);
            fma2(s, thA[2], g1.x);  fma2(s, thA[3], g1.y);
            u = unpack2(s);         const float s01 = u.x + u.y;   // (r,   j+4)
            s = mul2(thB[0], g0.x); fma2(s, thB[1], g0.y);
            fma2(s, thB[2], g1.x);  fma2(s, thB[3], g1.y);
            u = unpack2(s);         const float s11 = u.x + u.y;   // (r+8, j+4)

            const float p00 = __expf(s00 - ESHIFT);
            const float p10 = __expf(s10 - ESHIFT);
            const float p01 = __expf(s01 - ESHIFT);
            const float p11 = __expf(s11 - ESHIFT);
            lr  += p00 + p01;
            lr8 += p10 + p11;

            // A fragment: a0=(r,j) a1=(r+8,j) a2=(r,j+4) a3=(r+8,j+4)
            const unsigned a0 = f2tf32(p00), a1 = f2tf32(p10);
            const unsigned a2 = f2tf32(p01), a3 = f2tf32(p11);

            // B fragment per group: b0=g[key kb+j'][ch], row j'=lane%4,
            // col=lane/4 -> b0 = gs[(kb+j)*32 + cb + r], b1 same at key kb+j+4
            const unsigned* gRow0 = &gs[(kb + j) * 32 + r];
            const unsigned* gRow1 = &gs[(kb + 4 + j) * 32 + r];
#pragma unroll
            for (int grp = 0; grp < 4; grp++) {
                mma_tf32(dacc[grp], a0, a1, a2, a3,
                         gRow0[grp * 8], gRow1[grp * 8]);
            }
        }
    }

    // reduce l across the 4 threads of each row group (lanes j=0..3)
    lr  += __shfl_down_sync(0xffffffffu, lr, 1, 4);
    lr  += __shfl_down_sync(0xffffffffu, lr, 2, 4);
    lr8 += __shfl_down_sync(0xffffffffu, lr8, 1, 4);
    lr8 += __shfl_down_sync(0xffffffffu, lr8, 2, 4);

    const int ks = blockIdx.y;
    if (j == 0) {
        d_pl[ks * NSP + q0 + r]     = lr;
        d_pl[ks * NSP + q0 + 8 + r] = lr8;
    }

    // write accumulators: c0=(r, 2j) c1=(r, 2j+1) c2=(r+8, 2j) c3=(r+8, 2j+1)
    {
        float* baseA = &d_pacc[((size_t)ks * NSP + q0 + r) * 32];
        float* baseB = &d_pacc[((size_t)ks * NSP + q0 + 8 + r) * 32];
#pragma unroll
        for (int grp = 0; grp < 4; grp++) {
            const int ch = grp * 8 + 2 * j;
            *(float2*)&baseA[ch] = make_float2(dacc[grp][0], dacc[grp][1]);
            *(float2*)&baseB[ch] = make_float2(dacc[grp][2], dacc[grp][3]);
        }
    }
}

// ---------------- kernel 3: merge splits, channel-parallel -----------------
// grid: (72, 8), block 128 — each block handles 4 of 32 channels
__global__ __launch_bounds__(128) void attn_combine()
{
    const int q  = blockIdx.x * 128 + threadIdx.x;
    const int cb = blockIdx.y * 4;

    float l = 0.f;
#pragma unroll
    for (int i = 0; i < KS; i++) l += d_pl[i * NSP + q];

    float a0 = 0.f, a1 = 0.f, a2 = 0.f, a3 = 0.f;
#pragma unroll
    for (int i = 0; i < KS; i++) {
        float4 v = *(const float4*)&d_pacc[((size_t)i * NSP + q) * 32 + cb];
        a0 += v.x; a1 += v.y; a2 += v.z; a3 += v.w;
    }

    const float inv = 1.f / l;
    const int d = q / (HH * WW), r = q % (HH * WW);
    const int pidx = (d + 1) * PPLN + (r / WW + 1) * PROW + (r % WW + 1);
    d_ogpad[(cb + 0) * PCH + pidx] = a0 * inv;
    d_ogpad[(cb + 1) * PCH + pidx] = a1 * inv;
    d_ogpad[(cb + 2) * PCH + pidx] = a2 * inv;
    d_ogpad[(cb + 3) * PCH + pidx] = a3 * inv;
}

// ---------------- kernel 4: o-conv (64 out, 32 in) -------------------------
// grid: (96, 8) — 96 spatial tiles, 8 co-groups of 8
__global__ __launch_bounds__(96) void conv_o(
    const float* __restrict__ ow, const float* __restrict__ ob)
{
    __shared__ __align__(16) float ws[16 * 27 * 8];

    const int tid = threadIdx.x;
    const int gy = blockIdx.y;
    const int d = blockIdx.x / 6;
    const int h = (blockIdx.x % 6) * 4 + tid / 24;
    const int w = tid % 24;
    const int corner = d * PPLN + h * PROW + w;

    ull acc2[4];
#pragma unroll
    for (int j = 0; j < 4; j++) acc2[j] = 0ull;

    for (int cc = 0; cc < 2; cc++) {      // ci chunks of 16 (32 total)
        for (int i = tid; i < 16 * 27 * 8; i += 96) {
            const int ci  = i / (27 * 8);
            const int rem = i % (27 * 8);
            const int tap = rem / 8;
            const int co  = rem % 8;
            ws[(ci * 27 + tap) * 8 + co] =
                ow[((gy * 8 + co) * 32 + cc * 16 + ci) * 27 + tap];
        }
        __syncthreads();

        for (int ci = 0; ci < 16; ci++) {
            const float* xb = d_ogpad + (cc * 16 + ci) * PCH + corner;
            float xv[27];
#pragma unroll
            for (int t = 0; t < 27; t++)
                xv[t] = __ldg(xb + TAPOFF(t));
#pragma unroll
            for (int t = 0; t < 27; t++) {
                const ull x2 = pack2(xv[t], xv[t]);
                const ulonglong2 wv =
                    *(const ulonglong2*)&ws[(ci * 27 + t) * 8];
                fma2(acc2[0], x2, wv.x);
                fma2(acc2[1], x2, wv.y);
                const ulonglong2 wv2 =
                    *(const ulonglong2*)&ws[(ci * 27 + t) * 8 + 4];
                fma2(acc2[2], x2, wv2.x);
                fma2(acc2[3], x2, wv2.y);
            }
        }
        __syncthreads();
    }

    const int n = d * (HH * WW) + h * WW + w;
#pragma unroll
    for (int j = 0; j < 4; j++) {
        float2 u = unpack2(acc2[j]);
        d_y[(gy * 8 + 2 * j)     * NSP + n] = u.x + ob[gy * 8 + 2 * j];
        d_y[(gy * 8 + 2 * j + 1) * NSP + n] = u.y + ob[gy * 8 + 2 * j + 1];
    }
}

// ---------------- kernel 5: BN stats (512 thr, float4 loads) ---------------
__global__ __launch_bounds__(512) void bn_stats()
{
    const int c = blockIdx.x;
    float s = 0.f, s2 = 0.f;
    const float4* yb = (const float4*)&d_y[c * NSP];
    for (int i = threadIdx.x; i < NSP / 4; i += 512) {
        float4 v = yb[i];
        s  += v.x + v.y + v.z + v.w;
        s2 += v.x * v.x + v.y * v.y + v.z * v.z + v.w * v.w;
    }
#pragma unroll
    for (int o = 16; o > 0; o >>= 1) {
        s  += __shfl_down_sync(0xffffffffu, s,  o);
        s2 += __shfl_down_sync(0xffffffffu, s2, o);
    }
    __shared__ float shs[16], shs2[16];
    const int wid = threadIdx.x / 32, lid = threadIdx.x % 32;
    if (lid == 0) { shs[wid] = s; shs2[wid] = s2; }
    __syncthreads();
    if (threadIdx.x == 0) {
        float ts = 0.f, ts2 = 0.f;
#pragma unroll
        for (int i = 0; i < 16; i++) { ts += shs[i]; ts2 += shs2[i]; }
        const float mean = ts * (1.f / NSP);
        const float var  = ts2 * (1.f / NSP) - mean * mean;
        d_mean[c] = mean;
        d_rstd[c] = rsqrtf(var + 1e-5f);
    }
}

// ---------------- kernel 6: BN apply + residual + relu ---------------------
__global__ __launch_bounds__(256) void final_ew(
    const float* __restrict__ x,
    const float* __restrict__ gamma,
    const float* __restrict__ beta,
    float* __restrict__ out)
{
    const int idx = blockIdx.x * 256 + threadIdx.x;
    if (idx >= 64 * NSP) return;
    const int c = idx / NSP;
    const float yn = (d_y[idx] - d_mean[c]) * d_rstd[c] * gamma[c] + beta[c];
    const float v  = x[idx] + yn;
    out[idx] = v > 0.f ? v : 0.f;
}

// ---------------- launch ---------------------------------------------------
extern "C" void kernel_launch(void* const* d_in, const int* in_sizes, int n_in,
                              void* d_out, int out_size)
{
    (void)in_sizes; (void)n_in; (void)out_size;
    const float* x  = (const float*)d_in[0];
    const float* tw = (const float*)d_in[1];
    const float* tb = (const float*)d_in[2];
    const float* pw = (const float*)d_in[3];
    const float* pb = (const float*)d_in[4];
    const float* gw = (const float*)d_in[5];
    const float* gb = (const float*)d_in[6];
    const float* ow = (const float*)d_in[7];
    const float* ob = (const float*)d_in[8];
    const float* gamma = (const float*)d_in[9];
    const float* beta  = (const float*)d_in[10];
    float* out = (float*)d_out;

    pad_x<<<(64 * NSP + 255) / 256, 256>>>(x);
    conv_qkv<<<dim3(96, 6), 96>>>(tw, tb, pw, pb, gw, gb);
    attn_split<<<dim3(NSP / 128, KS), 256>>>();
    attn_combine<<<dim3(NSP / 128, 8), 128>>>();
    conv_o<<<dim3(96, 8), 96>>>(ow, ob);
    bn_stats<<<64, 512>>>();
    final_ew<<<(64 * NSP + 255) / 256, 256>>>(x, gamma, beta, out);
}

// round 13
// speedup vs baseline: 1.3707x; 1.0786x over previous
#include <cuda_runtime.h>
#include <math.h>

#define NSP 9216        // 16*24*24
#define DD 16
#define HH 24
#define WW 24
#define PROW 26         // padded row (W+2)
#define PPLN 676        // padded plane (H+2)*(W+2)
#define PCH  12168      // padded channel (D+2)*PPLN
#define KS 16           // key splits for attention
#define KPS (NSP / KS)  // 576 keys per split
#define ESHIFT 40.0f    // fixed softmax shift
#define LOG2E 1.4426950408889634f
#define E2 (ESHIFT * LOG2E)

typedef unsigned long long ull;

// ---------------- f32x2 packed helpers (sm_100+) ---------------------------
__device__ __forceinline__ ull pack2(float lo, float hi) {
    ull r;
    asm("mov.b64 %0, {%1, %2};" : "=l"(r) : "f"(lo), "f"(hi));
    return r;
}
__device__ __forceinline__ float2 unpack2(ull v) {
    float2 f;
    asm("mov.b64 {%0, %1}, %2;" : "=f"(f.x), "=f"(f.y) : "l"(v));
    return f;
}
__device__ __forceinline__ void fma2(ull& d, ull a, ull b) {
    asm("fma.rn.f32x2 %0, %1, %2, %3;" : "=l"(d) : "l"(a), "l"(b), "l"(d));
}
__device__ __forceinline__ unsigned f2tf32(float f) {
    unsigned u;
    asm("cvt.rna.tf32.f32 %0, %1;" : "=r"(u) : "f"(f));
    return u;
}
__device__ __forceinline__ float ex2(float x) {
    float r;
    asm("ex2.approx.f32 %0, %1;" : "=f"(r) : "f"(x));
    return r;
}
// D += A(16x8) @ B(8x8), tf32 inputs, f32 accum (m16n8k8 row.col)
__device__ __forceinline__ void mma_tf32(float* d,
    unsigned a0, unsigned a1, unsigned a2, unsigned a3,
    unsigned b0, unsigned b1) {
    asm("mma.sync.aligned.m16n8k8.row.col.f32.tf32.tf32.f32 "
        "{%0,%1,%2,%3}, {%4,%5,%6,%7}, {%8,%9}, {%0,%1,%2,%3};"
        : "+f"(d[0]), "+f"(d[1]), "+f"(d[2]), "+f"(d[3])
        : "r"(a0), "r"(a1), "r"(a2), "r"(a3), "r"(b0), "r"(b1));
}

// ---------------- scratch (device globals; zero-initialized) ---------------
__device__ __align__(16) float d_xpad[64 * PCH];      // padded x (borders 0)
__device__ __align__(16) float d_ogpad[32 * PCH];     // padded attn out
__device__ __align__(16) float d_theta[NSP * 8];      // [n][c]
__device__ __align__(16) float d_phi[NSP * 8];        // [n][c]
__device__ __align__(16) float d_g[NSP * 32];         // [n][c]
__device__ __align__(16) float d_pl[KS * NSP];        // partial sum
__device__ __align__(16) float d_pacc[KS * NSP * 32]; // partial acc
__device__ __align__(16) float d_y[64 * NSP];         // o-conv out, [c][n]

// tap offsets into padded layout (compile-time immediates after unroll)
#define TAPOFF(t) ((t / 9) * PPLN + ((t / 3) % 3) * PROW + (t % 3))

// ---------------- kernel 0: pad x into halo layout -------------------------
__global__ __launch_bounds__(256) void pad_x(const float* __restrict__ x)
{
    const int idx = blockIdx.x * 256 + threadIdx.x;
    if (idx >= 64 * NSP) return;
    const int c = idx / NSP, n = idx % NSP;
    const int d = n / (HH * WW), r = n % (HH * WW);
    const int h = r / WW, w = r % WW;
    d_xpad[c * PCH + (d + 1) * PPLN + (h + 1) * PROW + (w + 1)] = x[idx];
}

// ---------------- kernel 1: fused theta/phi/g conv3d -----------------------
// grid: (96, 6) — 96 spatial tiles (1x4x24), 6 co-groups of 8
__global__ __launch_bounds__(96) void conv_qkv(
    const float* __restrict__ tw, const float* __restrict__ tb,
    const float* __restrict__ pw, const float* __restrict__ pb,
    const float* __restrict__ gw, const float* __restrict__ gb)
{
    __shared__ __align__(16) float ws[16 * 27 * 8];   // [ci][tap][co]

    const int tid = threadIdx.x;
    const int gy = blockIdx.y;
    const int d = blockIdx.x / 6;
    const int h = (blockIdx.x % 6) * 4 + tid / 24;
    const int w = tid % 24;
    const int corner = d * PPLN + h * PROW + w;

    ull acc2[4];
#pragma unroll
    for (int j = 0; j < 4; j++) acc2[j] = 0ull;

    for (int cc = 0; cc < 4; cc++) {          // ci chunks of 16
        for (int i = tid; i < 16 * 27 * 8; i += 96) {
            const int ci  = i / (27 * 8);
            const int rem = i % (27 * 8);
            const int tap = rem / 8;
            const int co  = rem % 8;
            const int cig = cc * 16 + ci;
            float v;
            if (gy == 0)      v = tw[(co * 64 + cig) * 27 + tap];
            else if (gy == 1) v = pw[(co * 64 + cig) * 27 + tap];
            else              v = gw[(((gy - 2) * 8 + co) * 64 + cig) * 27 + tap];
            ws[(ci * 27 + tap) * 8 + co] = v;
        }
        __syncthreads();

        for (int ci = 0; ci < 16; ci++) {
            const float* xb = d_xpad + (cc * 16 + ci) * PCH + corner;
            float xv[27];
#pragma unroll
            for (int t = 0; t < 27; t++)
                xv[t] = __ldg(xb + TAPOFF(t));
#pragma unroll
            for (int t = 0; t < 27; t++) {
                const ull x2 = pack2(xv[t], xv[t]);
                const ulonglong2 wv =
                    *(const ulonglong2*)&ws[(ci * 27 + t) * 8];
                fma2(acc2[0], x2, wv.x);
                fma2(acc2[1], x2, wv.y);
                const ulonglong2 wv2 =
                    *(const ulonglong2*)&ws[(ci * 27 + t) * 8 + 4];
                fma2(acc2[2], x2, wv2.x);
                fma2(acc2[3], x2, wv2.y);
            }
        }
        __syncthreads();
    }

    float acc[8];
#pragma unroll
    for (int j = 0; j < 4; j++) {
        float2 u = unpack2(acc2[j]);
        acc[2 * j] = u.x; acc[2 * j + 1] = u.y;
    }

    const int n = d * (HH * WW) + h * WW + w;
    if (gy == 0) {
#pragma unroll
        for (int c = 0; c < 8; c++) d_theta[n * 8 + c] = acc[c] + tb[c];
    } else if (gy == 1) {
#pragma unroll
        for (int c = 0; c < 8; c++) d_phi[n * 8 + c] = acc[c] + pb[c];
    } else {
        const int cb = (gy - 2) * 8;
#pragma unroll
        for (int c = 0; c < 8; c++)
            d_g[n * 32 + cb + c] = acc[c] + gb[cb + c];
    }
}

// ---------------- kernel 2: attention, full tensor-core QK + PV ------------
// grid: (72, KS), block 256 (8 warps). Warp owns 16 queries.
// QK: 3x tf32-split mma (hi*hi + hi*lo + lo*hi) -> fp32-accurate logits,
// theta pre-scaled by log2e so p = ex2(c - 40*log2e).
// Key-permutation trick: QK C gives thread (r,j) keys {2j,2j+1}; using a
// consistent k-permutation tau=[0,2,4,6,1,3,5,7] on the PV mma (A and B),
// those values ARE the PV A fragment (a0=e(c0),a1=e(c2),a2=e(c1),a3=e(c3))
// and PV g rows become kb+2j / kb+2j+1. No data movement.
__global__ __launch_bounds__(256) void attn_split()
{
    __shared__ __align__(16) uint2    ps2[64 * 8];   // phi {hi,lo} tf32 bits
    __shared__ __align__(16) unsigned gs[64 * 32];   // g tile (tf32 bits)

    const int t = threadIdx.x;
    const int warp = t / 32, lane = t % 32;
    const int r = lane / 4, j = lane % 4;
    const int q0 = blockIdx.x * 128 + warp * 16;     // warp's query base
    const int k0 = blockIdx.y * KPS;

    // A fragments for QK: theta (x log2e), split hi/lo
    unsigned ah[4], al[4];
    {
        const float v0 = __ldg(&d_theta[(q0 + r) * 8 + j])     * LOG2E;
        const float v1 = __ldg(&d_theta[(q0 + 8 + r) * 8 + j]) * LOG2E;
        const float v2 = __ldg(&d_theta[(q0 + r) * 8 + j + 4]) * LOG2E;
        const float v3 = __ldg(&d_theta[(q0 + 8 + r) * 8 + j + 4]) * LOG2E;
        ah[0] = f2tf32(v0); al[0] = f2tf32(v0 - __uint_as_float(ah[0]));
        ah[1] = f2tf32(v1); al[1] = f2tf32(v1 - __uint_as_float(ah[1]));
        ah[2] = f2tf32(v2); al[2] = f2tf32(v2 - __uint_as_float(ah[2]));
        ah[3] = f2tf32(v3); al[3] = f2tf32(v3 - __uint_as_float(ah[3]));
    }

    float dacc[4][4];   // 4 channel groups x 4 C regs
#pragma unroll
    for (int g2 = 0; g2 < 4; g2++)
#pragma unroll
        for (int c = 0; c < 4; c++) dacc[g2][c] = 0.f;
    float lr = 0.f, lr8 = 0.f;

    for (int kt = 0; kt < KPS / 64; kt++) {
        __syncthreads();
        {   // phi tile: split each value into {hi, lo} tf32
            const float2 v = ((const float2*)(d_phi + (k0 + kt * 64) * 8))[t];
            uint2 e0, e1;
            e0.x = f2tf32(v.x); e0.y = f2tf32(v.x - __uint_as_float(e0.x));
            e1.x = f2tf32(v.y); e1.y = f2tf32(v.y - __uint_as_float(e1.x));
            ps2[2 * t]     = e0;
            ps2[2 * t + 1] = e1;
        }
        {   // g tile: tf32
            const float4* src = (const float4*)(d_g + (k0 + kt * 64) * 32);
#pragma unroll
            for (int i = 0; i < 2; i++) {
                float4 v = src[t + i * 256];
                uint4 u;
                u.x = f2tf32(v.x); u.y = f2tf32(v.y);
                u.z = f2tf32(v.z); u.w = f2tf32(v.w);
                ((uint4*)gs)[t + i * 256] = u;
            }
        }
        __syncthreads();

#pragma unroll 2
        for (int sub = 0; sub < 8; sub++) {
            const int kb = sub * 8;
            // B fragment (phi): b0 = phi[key kb+r][ch j], b1 = ...[ch j+4]
            const uint2 bj  = ps2[(kb + r) * 8 + j];
            const uint2 bj4 = ps2[(kb + r) * 8 + j + 4];

            float c[4] = {0.f, 0.f, 0.f, 0.f};
            mma_tf32(c, ah[0], ah[1], ah[2], ah[3], bj.x, bj4.x); // hi*hi
            mma_tf32(c, ah[0], ah[1], ah[2], ah[3], bj.y, bj4.y); // hi*lo
            mma_tf32(c, al[0], al[1], al[2], al[3], bj.x, bj4.x); // lo*hi

            // c0=(r,2j) c1=(r,2j+1) c2=(r+8,2j) c3=(r+8,2j+1), log2-scaled
            const float p00 = ex2(c[0] - E2);   // (r,   2j)
            const float p01 = ex2(c[1] - E2);   // (r,   2j+1)
            const float p10 = ex2(c[2] - E2);   // (r+8, 2j)
            const float p11 = ex2(c[3] - E2);   // (r+8, 2j+1)
            lr  += p00 + p01;
            lr8 += p10 + p11;

            // PV A fragment under tau-permuted k-axis:
            // a0=(r,k=j)->p(r,2j), a1=(r+8,k=j)->p(r+8,2j),
            // a2=(r,k=j+4)->p(r,2j+1), a3=(r+8,k=j+4)->p(r+8,2j+1)
            const unsigned a0 = f2tf32(p00), a1 = f2tf32(p10);
            const unsigned a2 = f2tf32(p01), a3 = f2tf32(p11);

            // PV B rows permuted the same way: k=j -> key kb+2j,
            // k=j+4 -> key kb+2j+1
            const unsigned* gRow0 = &gs[(kb + 2 * j) * 32 + r];
            const unsigned* gRow1 = &gs[(kb + 2 * j + 1) * 32 + r];
#pragma unroll
            for (int grp = 0; grp < 4; grp++) {
                mma_tf32(dacc[grp], a0, a1, a2, a3,
                         gRow0[grp * 8], gRow1[grp * 8]);
            }
        }
    }

    // reduce l across the 4 threads of each row group (lanes j=0..3)
    lr  += __shfl_down_sync(0xffffffffu, lr, 1, 4);
    lr  += __shfl_down_sync(0xffffffffu, lr, 2, 4);
    lr8 += __shfl_down_sync(0xffffffffu, lr8, 1, 4);
    lr8 += __shfl_down_sync(0xffffffffu, lr8, 2, 4);

    const int ks = blockIdx.y;
    if (j == 0) {
        d_pl[ks * NSP + q0 + r]     = lr;
        d_pl[ks * NSP + q0 + 8 + r] = lr8;
    }

    // write accumulators: c0=(r, 2j) c1=(r, 2j+1) c2=(r+8, 2j) c3=(r+8, 2j+1)
    {
        float* baseA = &d_pacc[((size_t)ks * NSP + q0 + r) * 32];
        float* baseB = &d_pacc[((size_t)ks * NSP + q0 + 8 + r) * 32];
#pragma unroll
        for (int grp = 0; grp < 4; grp++) {
            const int ch = grp * 8 + 2 * j;
            *(float2*)&baseA[ch] = make_float2(dacc[grp][0], dacc[grp][1]);
            *(float2*)&baseB[ch] = make_float2(dacc[grp][2], dacc[grp][3]);
        }
    }
}

// ---------------- kernel 3: merge splits, channel-parallel -----------------
// grid: (72, 8), block 128 — each block handles 4 of 32 channels
__global__ __launch_bounds__(128) void attn_combine()
{
    const int q  = blockIdx.x * 128 + threadIdx.x;
    const int cb = blockIdx.y * 4;

    float l = 0.f;
#pragma unroll
    for (int i = 0; i < KS; i++) l += d_pl[i * NSP + q];

    float a0 = 0.f, a1 = 0.f, a2 = 0.f, a3 = 0.f;
#pragma unroll
    for (int i = 0; i < KS; i++) {
        float4 v = *(const float4*)&d_pacc[((size_t)i * NSP + q) * 32 + cb];
        a0 += v.x; a1 += v.y; a2 += v.z; a3 += v.w;
    }

    const float inv = 1.f / l;
    const int d = q / (HH * WW), r = q % (HH * WW);
    const int pidx = (d + 1) * PPLN + (r / WW + 1) * PROW + (r % WW + 1);
    d_ogpad[(cb + 0) * PCH + pidx] = a0 * inv;
    d_ogpad[(cb + 1) * PCH + pidx] = a1 * inv;
    d_ogpad[(cb + 2) * PCH + pidx] = a2 * inv;
    d_ogpad[(cb + 3) * PCH + pidx] = a3 * inv;
}

// ---------------- kernel 4: o-conv (64 out, 32 in) -------------------------
// grid: (96, 8) — 96 spatial tiles, 8 co-groups of 8
__global__ __launch_bounds__(96) void conv_o(
    const float* __restrict__ ow, const float* __restrict__ ob)
{
    __shared__ __align__(16) float ws[16 * 27 * 8];

    const int tid = threadIdx.x;
    const int gy = blockIdx.y;
    const int d = blockIdx.x / 6;
    const int h = (blockIdx.x % 6) * 4 + tid / 24;
    const int w = tid % 24;
    const int corner = d * PPLN + h * PROW + w;

    ull acc2[4];
#pragma unroll
    for (int j = 0; j < 4; j++) acc2[j] = 0ull;

    for (int cc = 0; cc < 2; cc++) {      // ci chunks of 16 (32 total)
        for (int i = tid; i < 16 * 27 * 8; i += 96) {
            const int ci  = i / (27 * 8);
            const int rem = i % (27 * 8);
            const int tap = rem / 8;
            const int co  = rem % 8;
            ws[(ci * 27 + tap) * 8 + co] =
                ow[((gy * 8 + co) * 32 + cc * 16 + ci) * 27 + tap];
        }
        __syncthreads();

        for (int ci = 0; ci < 16; ci++) {
            const float* xb = d_ogpad + (cc * 16 + ci) * PCH + corner;
            float xv[27];
#pragma unroll
            for (int t = 0; t < 27; t++)
                xv[t] = __ldg(xb + TAPOFF(t));
#pragma unroll
            for (int t = 0; t < 27; t++) {
                const ull x2 = pack2(xv[t], xv[t]);
                const ulonglong2 wv =
                    *(const ulonglong2*)&ws[(ci * 27 + t) * 8];
                fma2(acc2[0], x2, wv.x);
                fma2(acc2[1], x2, wv.y);
                const ulonglong2 wv2 =
                    *(const ulonglong2*)&ws[(ci * 27 + t) * 8 + 4];
                fma2(acc2[2], x2, wv2.x);
                fma2(acc2[3], x2, wv2.y);
            }
        }
        __syncthreads();
    }

    const int n = d * (HH * WW) + h * WW + w;
#pragma unroll
    for (int j = 0; j < 4; j++) {
        float2 u = unpack2(acc2[j]);
        d_y[(gy * 8 + 2 * j)     * NSP + n] = u.x + ob[gy * 8 + 2 * j];
        d_y[(gy * 8 + 2 * j + 1) * NSP + n] = u.y + ob[gy * 8 + 2 * j + 1];
    }
}

// ---------------- kernel 5: fused BN stats + apply + residual + relu -------
// grid: 64 (one block per channel), block 512
__global__ __launch_bounds__(512) void bn_final(
    const float* __restrict__ x,
    const float* __restrict__ gamma,
    const float* __restrict__ beta,
    float* __restrict__ out)
{
    const int c = blockIdx.x;
    float s = 0.f, s2 = 0.f;
    const float4* yb = (const float4*)&d_y[c * NSP];
    for (int i = threadIdx.x; i < NSP / 4; i += 512) {
        float4 v = yb[i];
        s  += v.x + v.y + v.z + v.w;
        s2 += v.x * v.x + v.y * v.y + v.z * v.z + v.w * v.w;
    }
#pragma unroll
    for (int o = 16; o > 0; o >>= 1) {
        s  += __shfl_down_sync(0xffffffffu, s,  o);
        s2 += __shfl_down_sync(0xffffffffu, s2, o);
    }
    __shared__ float shs[16], shs2[16];
    __shared__ float sh_mean, sh_rstd;
    const int wid = threadIdx.x / 32, lid = threadIdx.x % 32;
    if (lid == 0) { shs[wid] = s; shs2[wid] = s2; }
    __syncthreads();
    if (threadIdx.x == 0) {
        float ts = 0.f, ts2 = 0.f;
#pragma unroll
        for (int i = 0; i < 16; i++) { ts += shs[i]; ts2 += shs2[i]; }
        const float mean = ts * (1.f / NSP);
        const float var  = ts2 * (1.f / NSP) - mean * mean;
        sh_mean = mean;
        sh_rstd = rsqrtf(var + 1e-5f);
    }
    __syncthreads();

    const float mean = sh_mean;
    const float sc   = sh_rstd * gamma[c];
    const float bs   = beta[c];
    const float4* xb = (const float4*)&x[c * NSP];
    float4* ob4 = (float4*)&out[c * NSP];
    for (int i = threadIdx.x; i < NSP / 4; i += 512) {
        float4 y4 = yb[i];
        float4 x4 = xb[i];
        float4 o4;
        o4.x = x4.x + (y4.x - mean) * sc + bs;
        o4.y = x4.y + (y4.y - mean) * sc + bs;
        o4.z = x4.z + (y4.z - mean) * sc + bs;
        o4.w = x4.w + (y4.w - mean) * sc + bs;
        o4.x = o4.x > 0.f ? o4.x : 0.f;
        o4.y = o4.y > 0.f ? o4.y : 0.f;
        o4.z = o4.z > 0.f ? o4.z : 0.f;
        o4.w = o4.w > 0.f ? o4.w : 0.f;
        ob4[i] = o4;
    }
}

// ---------------- launch ---------------------------------------------------
extern "C" void kernel_launch(void* const* d_in, const int* in_sizes, int n_in,
                              void* d_out, int out_size)
{
    (void)in_sizes; (void)n_in; (void)out_size;
    const float* x  = (const float*)d_in[0];
    const float* tw = (const float*)d_in[1];
    const float* tb = (const float*)d_in[2];
    const float* pw = (const float*)d_in[3];
    const float* pb = (const float*)d_in[4];
    const float* gw = (const float*)d_in[5];
    const float* gb = (const float*)d_in[6];
    const float* ow = (const float*)d_in[7];
    const float* ob = (const float*)d_in[8];
    const float* gamma = (const float*)d_in[9];
    const float* beta  = (const float*)d_in[10];
    float* out = (float*)d_out;

    pad_x<<<(64 * NSP + 255) / 256, 256>>>(x);
    conv_qkv<<<dim3(96, 6), 96>>>(tw, tb, pw, pb, gw, gb);
    attn_split<<<dim3(NSP / 128, KS), 256>>>();
    attn_combine<<<dim3(NSP / 128, 8), 128>>>();
    conv_o<<<dim3(96, 8), 96>>>(ow, ob);
    bn_final<<<64, 512>>>(x, gamma, beta, out);
}